// round 3
// baseline (speedup 1.0000x reference)
#include <cuda_runtime.h>
#include <math.h>

#define SEQ   512
#define BATCH 64
#define INP   64
#define HID   1024
#define G4    (4 * HID)

#define NBLK  128          // HID / JT blocks, one per SM (<=148 -> co-resident)
#define NTHR  256
#define JT    8            // h-columns per block
#define BK    32           // K slab for h staging

#define WS_STRIDE 36       // padded row stride for ws   [1024][36] (16B aligned)
#define HS_STRIDE 66       // padded row stride for hs   [32][66]   (8B aligned)
#define GS_STRIDE 65       // padded row stride for gsm  [32][65]

// ---------------------------------------------------------------------------
// Static device scratch
// ---------------------------------------------------------------------------
__device__ float g_xg[(size_t)SEQ * BATCH * G4];     // input-gate precompute
__device__ float g_h1[(size_t)SEQ * BATCH * HID];    // layer-0 hidden sequence
__device__ float g_hzero[BATCH * HID];               // zeros for h_{-1}
__device__ unsigned g_bar_count;
__device__ unsigned g_bar_gen;

// ---------------------------------------------------------------------------
__global__ void init_state_kernel() {
    int i = blockIdx.x * blockDim.x + threadIdx.x;
    if (i < BATCH * HID) g_hzero[i] = 0.f;
    if (i == 0) g_bar_count = 0u;
}

// Software grid barrier (all blocks co-resident by construction).
__device__ __forceinline__ void grid_barrier(unsigned nb) {
    __threadfence();
    __syncthreads();
    if (threadIdx.x == 0) {
        unsigned gen = atomicAdd(&g_bar_gen, 0u);
        __threadfence();
        unsigned t = atomicAdd(&g_bar_count, 1u);
        if (t == nb - 1u) {
            atomicExch(&g_bar_count, 0u);
            __threadfence();
            atomicAdd(&g_bar_gen, 1u);
        } else {
            while (atomicAdd(&g_bar_gen, 0u) == gen) { }
        }
    }
    __syncthreads();
}

// ---------------------------------------------------------------------------
// C[M][4096] = A[M][K] @ W[4096][K]^T + (b1 + b2)   (fp32 SIMT, 64x64 tiles)
// ---------------------------------------------------------------------------
__global__ void sgemm_bias_kernel(const float* __restrict__ A,
                                  const float* __restrict__ W,
                                  const float* __restrict__ b1,
                                  const float* __restrict__ b2,
                                  float* __restrict__ C,
                                  int M, int K) {
    const int BKg = 16;
    __shared__ float As[BKg][64];
    __shared__ float Bs[BKg][64];

    int tid = threadIdx.x;
    int tx = tid & 15;
    int ty = tid >> 4;
    int m0 = blockIdx.y * 64;
    int n0 = blockIdx.x * 64;

    float acc[4][4];
#pragma unroll
    for (int i = 0; i < 4; i++)
#pragma unroll
        for (int j = 0; j < 4; j++) acc[i][j] = 0.f;

    int lr = tid >> 2;
    int lc = tid & 3;

    for (int k0 = 0; k0 < K; k0 += BKg) {
        float4 va = *(const float4*)(A + (size_t)(m0 + lr) * K + k0 + lc * 4);
        As[lc * 4 + 0][lr] = va.x;
        As[lc * 4 + 1][lr] = va.y;
        As[lc * 4 + 2][lr] = va.z;
        As[lc * 4 + 3][lr] = va.w;
        float4 vb = *(const float4*)(W + (size_t)(n0 + lr) * K + k0 + lc * 4);
        Bs[lc * 4 + 0][lr] = vb.x;
        Bs[lc * 4 + 1][lr] = vb.y;
        Bs[lc * 4 + 2][lr] = vb.z;
        Bs[lc * 4 + 3][lr] = vb.w;
        __syncthreads();

#pragma unroll
        for (int kk = 0; kk < BKg; kk++) {
            float a[4], b[4];
#pragma unroll
            for (int i = 0; i < 4; i++) a[i] = As[kk][ty * 4 + i];
#pragma unroll
            for (int j = 0; j < 4; j++) b[j] = Bs[kk][tx * 4 + j];
#pragma unroll
            for (int i = 0; i < 4; i++)
#pragma unroll
                for (int j = 0; j < 4; j++) acc[i][j] += a[i] * b[j];
        }
        __syncthreads();
    }

#pragma unroll
    for (int i = 0; i < 4; i++) {
        int m = m0 + ty * 4 + i;
#pragma unroll
        for (int j = 0; j < 4; j++) {
            int n = n0 + tx * 4 + j;
            C[(size_t)m * G4 + n] = acc[i][j] + b1[n] + b2[n];
        }
    }
}

// ---------------------------------------------------------------------------
// Persistent LSTM layer: all 512 timesteps in one kernel.
// Block bx owns h-columns [bx*8, bx*8+8) for all 4 gates and all 64 batches.
// Whh slice kept in SMEM for the whole sequence; c kept in registers.
// ---------------------------------------------------------------------------
__global__ void __launch_bounds__(NTHR, 1)
lstm_layer_kernel(const float* __restrict__ xg,      // [SEQ, B, 4H]
                  const float* __restrict__ Whh,     // [4H, H]
                  const float* __restrict__ hzero,   // [B, H] zeros
                  float* __restrict__ hseq)          // [SEQ, B, H] out
{
    extern __shared__ float smem[];
    float* ws  = smem;                            // [1024][WS_STRIDE]
    float* hs  = ws + 1024 * WS_STRIDE;           // [BK][HS_STRIDE]
    float* gsm = hs + BK * HS_STRIDE;             // [32][GS_STRIDE]

    const int tid = threadIdx.x;
    const int j0  = blockIdx.x * JT;
    const unsigned nb = gridDim.x;

    // ---- One-time: load this block's Whh slice, transposed to ws[k][r] ----
    // r = g*8 + jl  ->  global row g*HID + j0 + jl
    {
        int r  = tid >> 3;          // 0..31
        int kc = tid & 7;           // 8 chunks of 128 k each
        int g  = r >> 3, jl = r & 7;
        const float4* src =
            (const float4*)(Whh + (size_t)(g * HID + j0 + jl) * HID + kc * 128);
#pragma unroll
        for (int i = 0; i < 32; i++) {
            float4 v = src[i];
            int k = kc * 128 + i * 4;
            ws[(k + 0) * WS_STRIDE + r] = v.x;
            ws[(k + 1) * WS_STRIDE + r] = v.y;
            ws[(k + 2) * WS_STRIDE + r] = v.z;
            ws[(k + 3) * WS_STRIDE + r] = v.w;
        }
    }
    __syncthreads();

    const int bq = tid & 31;        // batch pair: b = bq*2 + i
    const int rq = tid >> 5;        // row quad:   r = rq*4 + j
    const int hb = tid >> 2;        // 0..63 h row for staging
    const int hc = tid & 3;         // float4 slot (and slot+4)

    float creg[2] = {0.f, 0.f};     // cell state for pairs p = tid, tid+256

    for (int t = 0; t < SEQ; t++) {
        const float* h_in = (t == 0) ? hzero
                                     : (hseq + (size_t)(t - 1) * BATCH * HID);
        const float* xg_t = xg + (size_t)t * BATCH * G4;

        float acc[2][4];
#pragma unroll
        for (int i = 0; i < 2; i++)
#pragma unroll
            for (int j = 0; j < 4; j++) acc[i][j] = 0.f;

        for (int k0 = 0; k0 < HID; k0 += BK) {
            // stage h slab -> hs[k][b]
            const float4* hrow = (const float4*)(h_in + (size_t)hb * HID + k0);
#pragma unroll
            for (int i = 0; i < 2; i++) {
                int c4 = hc + i * 4;
                float4 v = hrow[c4];
                int k = c4 * 4;
                hs[(k + 0) * HS_STRIDE + hb] = v.x;
                hs[(k + 1) * HS_STRIDE + hb] = v.y;
                hs[(k + 2) * HS_STRIDE + hb] = v.z;
                hs[(k + 3) * HS_STRIDE + hb] = v.w;
            }
            __syncthreads();

#pragma unroll
            for (int kk = 0; kk < BK; kk++) {
                float2 a = *(const float2*)&hs[kk * HS_STRIDE + bq * 2];
                float4 w = *(const float4*)&ws[(k0 + kk) * WS_STRIDE + rq * 4];
                acc[0][0] += a.x * w.x;
                acc[0][1] += a.x * w.y;
                acc[0][2] += a.x * w.z;
                acc[0][3] += a.x * w.w;
                acc[1][0] += a.y * w.x;
                acc[1][1] += a.y * w.y;
                acc[1][2] += a.y * w.z;
                acc[1][3] += a.y * w.w;
            }
            __syncthreads();
        }

        // stage gate partials -> gsm[r][b]
#pragma unroll
        for (int i = 0; i < 2; i++)
#pragma unroll
            for (int j = 0; j < 4; j++)
                gsm[(rq * 4 + j) * GS_STRIDE + bq * 2 + i] = acc[i][j];
        __syncthreads();

        // pointwise cell update: pairs p = tid + 256*q
        float* h_out = hseq + (size_t)t * BATCH * HID;
#pragma unroll
        for (int q = 0; q < 2; q++) {
            int p  = tid + NTHR * q;
            int b  = p >> 3;
            int jl = p & 7;
            int j  = j0 + jl;
            const float* xr = xg_t + (size_t)b * G4 + j;
            float ig = gsm[(0 * JT + jl) * GS_STRIDE + b] + xr[0 * HID];
            float fg = gsm[(1 * JT + jl) * GS_STRIDE + b] + xr[1 * HID];
            float gg = gsm[(2 * JT + jl) * GS_STRIDE + b] + xr[2 * HID];
            float og = gsm[(3 * JT + jl) * GS_STRIDE + b] + xr[3 * HID];
            ig = 1.f / (1.f + expf(-ig));
            fg = 1.f / (1.f + expf(-fg));
            gg = tanhf(gg);
            og = 1.f / (1.f + expf(-og));
            float cn = fg * creg[q] + ig * gg;
            creg[q] = cn;
            h_out[(size_t)b * HID + j] = og * tanhf(cn);
        }

        grid_barrier(nb);   // h_out visible everywhere before next step
    }
}

// ---------------------------------------------------------------------------
__global__ void final_linear_kernel(const float* __restrict__ h_last,
                                    const float* __restrict__ Wl,
                                    const float* __restrict__ bl,
                                    float* __restrict__ y) {
    int b = blockIdx.x;
    __shared__ float red[128];
    float s = 0.f;
    for (int k = threadIdx.x; k < HID; k += 128)
        s += h_last[(size_t)b * HID + k] * Wl[k];
    red[threadIdx.x] = s;
    __syncthreads();
    for (int off = 64; off > 0; off >>= 1) {
        if (threadIdx.x < off) red[threadIdx.x] += red[threadIdx.x + off];
        __syncthreads();
    }
    if (threadIdx.x == 0) y[b] = red[0] + bl[0];
}

// ---------------------------------------------------------------------------
extern "C" void kernel_launch(void* const* d_in, const int* in_sizes, int n_in,
                              void* d_out, int out_size) {
    (void)in_sizes; (void)n_in; (void)out_size;
    const float* x    = (const float*)d_in[0];
    const float* Wih0 = (const float*)d_in[1];
    const float* Whh0 = (const float*)d_in[2];
    const float* bih0 = (const float*)d_in[3];
    const float* bhh0 = (const float*)d_in[4];
    const float* Wih1 = (const float*)d_in[5];
    const float* Whh1 = (const float*)d_in[6];
    const float* bih1 = (const float*)d_in[7];
    const float* bhh1 = (const float*)d_in[8];
    const float* Wlin = (const float*)d_in[9];
    const float* blin = (const float*)d_in[10];

    float* out      = (float*)d_out;
    float* lstm_out = out;                                  // [SEQ, BATCH, HID]
    float* ypred    = out + (size_t)SEQ * BATCH * HID;      // [BATCH]

    float *xg, *h1, *hzero;
    cudaGetSymbolAddress((void**)&xg,    g_xg);
    cudaGetSymbolAddress((void**)&h1,    g_h1);
    cudaGetSymbolAddress((void**)&hzero, g_hzero);

    const int smem_bytes =
        (1024 * WS_STRIDE + BK * HS_STRIDE + 32 * GS_STRIDE) * (int)sizeof(float);
    cudaFuncSetAttribute(lstm_layer_kernel,
                         cudaFuncAttributeMaxDynamicSharedMemorySize, smem_bytes);

    const int M = SEQ * BATCH;
    dim3 gemm_grid(G4 / 64, M / 64);

    // ---- Layer 0 ----
    sgemm_bias_kernel<<<gemm_grid, 256>>>(x, Wih0, bih0, bhh0, xg, M, INP);
    init_state_kernel<<<(BATCH * HID + 255) / 256, 256>>>();
    lstm_layer_kernel<<<NBLK, NTHR, smem_bytes>>>(xg, Whh0, hzero, h1);

    // ---- Layer 1 ----
    sgemm_bias_kernel<<<gemm_grid, 256>>>(h1, Wih1, bih1, bhh1, xg, M, HID);
    init_state_kernel<<<(BATCH * HID + 255) / 256, 256>>>();
    lstm_layer_kernel<<<NBLK, NTHR, smem_bytes>>>(xg, Whh1, hzero, lstm_out);

    // ---- Head ----
    final_linear_kernel<<<BATCH, 128>>>(lstm_out + (size_t)(SEQ - 1) * BATCH * HID,
                                        Wlin, blin, ypred);
}

// round 4
// speedup vs baseline: 2.5120x; 2.5120x over previous
#include <cuda_runtime.h>
#include <cuda_fp16.h>
#include <math.h>
#include <stdint.h>

#define SEQ   512
#define BATCH 64
#define INP   64
#define HID   1024
#define G4    (4 * HID)
#define NBLK  128
#define NTHR  256

// ---- static scratch ----
__device__ float g_xg[(size_t)SEQ * BATCH * G4];
__device__ half  g_h_hi[(size_t)SEQ * BATCH * HID];
__device__ half  g_h_lo[(size_t)SEQ * BATCH * HID];
__device__ half  g_w_hi[(size_t)G4 * HID];
__device__ half  g_w_lo[(size_t)G4 * HID];
__device__ half  g_x_hi[(size_t)SEQ * BATCH * INP];
__device__ half  g_x_lo[(size_t)SEQ * BATCH * INP];
__device__ unsigned g_bar_count;
__device__ unsigned g_bar_gen;

// ---- helpers ----
__device__ __forceinline__ void mma16816(float c[4], const uint32_t a[4], const uint32_t b[2]) {
    asm volatile("mma.sync.aligned.m16n8k16.row.col.f32.f16.f16.f32 "
        "{%0,%1,%2,%3}, {%4,%5,%6,%7}, {%8,%9}, {%0,%1,%2,%3};\n"
        : "+f"(c[0]), "+f"(c[1]), "+f"(c[2]), "+f"(c[3])
        : "r"(a[0]), "r"(a[1]), "r"(a[2]), "r"(a[3]), "r"(b[0]), "r"(b[1]));
}
__device__ __forceinline__ void ldsm4(uint32_t r[4], const half* p) {
    uint32_t a = (uint32_t)__cvta_generic_to_shared(p);
    asm volatile("ldmatrix.sync.aligned.m8n8.x4.shared.b16 {%0,%1,%2,%3}, [%4];\n"
        : "=r"(r[0]), "=r"(r[1]), "=r"(r[2]), "=r"(r[3]) : "r"(a));
}
__device__ __forceinline__ void ldsm2(uint32_t r[2], const half* p) {
    uint32_t a = (uint32_t)__cvta_generic_to_shared(p);
    asm volatile("ldmatrix.sync.aligned.m8n8.x2.shared.b16 {%0,%1}, [%2];\n"
        : "=r"(r[0]), "=r"(r[1]) : "r"(a));
}
__device__ __forceinline__ void cp16(void* dst, const void* src) {
    uint32_t d = (uint32_t)__cvta_generic_to_shared(dst);
    asm volatile("cp.async.cg.shared.global [%0], [%1], 16;\n" :: "r"(d), "l"(src));
}
#define CP_COMMIT() asm volatile("cp.async.commit_group;\n")
#define CP_WAIT0()  asm volatile("cp.async.wait_group 0;\n")
#define CP_WAIT1()  asm volatile("cp.async.wait_group 1;\n")

__device__ __forceinline__ void grid_barrier(unsigned nb) {
    __threadfence();
    __syncthreads();
    if (threadIdx.x == 0) {
        unsigned gen = atomicAdd(&g_bar_gen, 0u);
        __threadfence();
        unsigned t = atomicAdd(&g_bar_count, 1u);
        if (t == nb - 1u) {
            atomicExch(&g_bar_count, 0u);
            __threadfence();
            atomicAdd(&g_bar_gen, 1u);
        } else {
            while (atomicAdd(&g_bar_gen, 0u) == gen) { }
        }
    }
    __syncthreads();
}

__global__ void init_bar_kernel() { g_bar_count = 0u; }

__global__ void split_fp16_kernel(const float* __restrict__ src,
                                  half* __restrict__ hi, half* __restrict__ lo, int n) {
    int i4 = (blockIdx.x * 256 + threadIdx.x) * 4;
    if (i4 >= n) return;
    float4 v = *(const float4*)(src + i4);
    half h0 = __float2half(v.x), h1 = __float2half(v.y);
    half h2 = __float2half(v.z), h3 = __float2half(v.w);
    hi[i4+0]=h0; hi[i4+1]=h1; hi[i4+2]=h2; hi[i4+3]=h3;
    lo[i4+0]=__float2half(v.x-__half2float(h0));
    lo[i4+1]=__float2half(v.y-__half2float(h1));
    lo[i4+2]=__float2half(v.z-__half2float(h2));
    lo[i4+3]=__float2half(v.w-__half2float(h3));
}

// ---------------------------------------------------------------------------
// C[M][4096] = A[M][K] @ W[4096][K]^T + b1 + b2   (fp16-split, 3-pass mma)
// 64x64 tile, BK=32, 8 warps (2m x 4n grouped 2x2 tiles), double-buffered.
// ---------------------------------------------------------------------------
__global__ void __launch_bounds__(256)
hgemm_split_kernel(const half* __restrict__ Ahi, const half* __restrict__ Alo,
                   const half* __restrict__ Whi, const half* __restrict__ Wlo,
                   const float* __restrict__ b1, const float* __restrict__ b2,
                   float* __restrict__ C, int M, int K) {
    __shared__ half sA[2][2][64 * 40];
    __shared__ half sB[2][2][64 * 40];
    const int tid = threadIdx.x, lane = tid & 31, w = tid >> 5;
    const int mi = w & 1, ni = w >> 1;
    const int r = lane >> 2, q = lane & 3;
    const int m0 = blockIdx.y * 64, n0 = blockIdx.x * 64;
    const int srow = tid >> 2, skq = (tid & 3) * 8;

    float acc[2][2][4];
#pragma unroll
    for (int a = 0; a < 2; a++)
#pragma unroll
        for (int b = 0; b < 2; b++)
#pragma unroll
            for (int c = 0; c < 4; c++) acc[a][b][c] = 0.f;

    const int NIT = K / 32;
    cp16(&sA[0][0][srow*40+skq], Ahi + (size_t)(m0+srow)*K + skq);
    cp16(&sA[0][1][srow*40+skq], Alo + (size_t)(m0+srow)*K + skq);
    cp16(&sB[0][0][srow*40+skq], Whi + (size_t)(n0+srow)*K + skq);
    cp16(&sB[0][1][srow*40+skq], Wlo + (size_t)(n0+srow)*K + skq);
    CP_COMMIT();

    for (int it = 0; it < NIT; it++) {
        if (it + 1 < NIT) {
            int k0 = (it+1)*32, bf = (it+1) & 1;
            cp16(&sA[bf][0][srow*40+skq], Ahi + (size_t)(m0+srow)*K + k0 + skq);
            cp16(&sA[bf][1][srow*40+skq], Alo + (size_t)(m0+srow)*K + k0 + skq);
            cp16(&sB[bf][0][srow*40+skq], Whi + (size_t)(n0+srow)*K + k0 + skq);
            cp16(&sB[bf][1][srow*40+skq], Wlo + (size_t)(n0+srow)*K + k0 + skq);
            CP_COMMIT(); CP_WAIT1();
        } else CP_WAIT0();
        __syncthreads();
        const half *Abh = sA[it&1][0], *Abl = sA[it&1][1];
        const half *Bbh = sB[it&1][0], *Bbl = sB[it&1][1];
#pragma unroll
        for (int s = 0; s < 2; s++) {
            const int kb = s * 16;
            uint32_t Ah[2][4], Al[2][4], Bh[2][2], Bl[2][2];
#pragma unroll
            for (int mt = 0; mt < 2; mt++) {
                ldsm4(Ah[mt], Abh + (mi*32 + mt*16 + (lane&15))*40 + kb + ((lane>>4)<<3));
                ldsm4(Al[mt], Abl + (mi*32 + mt*16 + (lane&15))*40 + kb + ((lane>>4)<<3));
            }
#pragma unroll
            for (int nt = 0; nt < 2; nt++) {
                ldsm2(Bh[nt], Bbh + (ni*16 + nt*8 + (lane&7))*40 + kb + (((lane>>3)&1)<<3));
                ldsm2(Bl[nt], Bbl + (ni*16 + nt*8 + (lane&7))*40 + kb + (((lane>>3)&1)<<3));
            }
#pragma unroll
            for (int mt = 0; mt < 2; mt++)
#pragma unroll
                for (int nt = 0; nt < 2; nt++) {
                    mma16816(acc[mt][nt], Ah[mt], Bh[nt]);
                    mma16816(acc[mt][nt], Ah[mt], Bl[nt]);
                    mma16816(acc[mt][nt], Al[mt], Bh[nt]);
                }
        }
        __syncthreads();
    }
#pragma unroll
    for (int mt = 0; mt < 2; mt++)
#pragma unroll
        for (int nt = 0; nt < 2; nt++) {
            int row = m0 + mi*32 + mt*16 + r;
            int col = n0 + ni*16 + nt*8 + q*2;
            float bs0 = b1[col] + b2[col], bs1 = b1[col+1] + b2[col+1];
            *(float2*)(C + (size_t)row*G4 + col) =
                make_float2(acc[mt][nt][0]+bs0, acc[mt][nt][1]+bs1);
            *(float2*)(C + (size_t)(row+8)*G4 + col) =
                make_float2(acc[mt][nt][2]+bs0, acc[mt][nt][3]+bs1);
        }
}

// ---------------------------------------------------------------------------
// Persistent mma LSTM layer. Block owns 32 gate rows (4g x 8j), M=64, K=1024.
// 8 warps: mi = w&1 (m32), ni = w>>1 (n8). Whh split->smem once; h via cp.async.
// ---------------------------------------------------------------------------
#define WSS 1032
#define HSS 136
#define WS_PART_B (32 * WSS * 2)
#define HS_PART_B (64 * HSS * 2)
#define HS_OFF    (2 * WS_PART_B)
#define PS_OFF    (HS_OFF + 4 * HS_PART_B)
#define SMEM_TOT  (PS_OFF + 64 * 34 * 4)

__global__ void __launch_bounds__(NTHR, 1)
lstm_layer_mma(const float* __restrict__ xg,     // [SEQ][B][4H] incl. biases
               const float* __restrict__ Whh,    // [4H][H] fp32
               half* __restrict__ hhi, half* __restrict__ hlo,  // [SEQ][B][H]
               float* __restrict__ hseq)         // fp32 out or null
{
    extern __shared__ char smem[];
    half*  wsh  = (half*)smem;
    half*  wsl  = (half*)(smem + WS_PART_B);
    float* psum = (float*)(smem + PS_OFF);

    const int tid = threadIdx.x, lane = tid & 31, w = tid >> 5;
    const int mi = w & 1, ni = w >> 1;
    const int r = lane >> 2, q = lane & 3;
    const int j0 = blockIdx.x * 8;
    const unsigned nb = gridDim.x;

    // one-time: load + split Whh slice into smem (rows n = g*8+jl)
    for (int idx = tid; idx < 32 * 256; idx += NTHR) {
        int n = idx >> 8, kq = (idx & 255) * 4;
        int grow = (n >> 3) * HID + j0 + (n & 7);
        float4 v = *(const float4*)(Whh + (size_t)grow * HID + kq);
        half h0=__float2half(v.x), h1=__float2half(v.y), h2=__float2half(v.z), h3=__float2half(v.w);
        half* ph = wsh + n * WSS + kq;
        half* pl = wsl + n * WSS + kq;
        ph[0]=h0; ph[1]=h1; ph[2]=h2; ph[3]=h3;
        pl[0]=__float2half(v.x-__half2float(h0));
        pl[1]=__float2half(v.y-__half2float(h1));
        pl[2]=__float2half(v.z-__half2float(h2));
        pl[3]=__float2half(v.w-__half2float(h3));
    }
    __syncthreads();

    float creg[2] = {0.f, 0.f};

    for (int t = 0; t < SEQ; t++) {
        float acc[2][4];
#pragma unroll
        for (int a = 0; a < 2; a++)
#pragma unroll
            for (int c = 0; c < 4; c++) acc[a][c] = 0.f;

        if (t > 0) {
            const half* srcH = hhi + (size_t)(t-1) * BATCH * HID;
            const half* srcL = hlo + (size_t)(t-1) * BATCH * HID;
#pragma unroll
            for (int i = 0; i < 4; i++) {
                int qq = tid + NTHR * i, row = qq >> 4, kq = (qq & 15) * 8;
                cp16((half*)(smem + HS_OFF) + row*HSS + kq, srcH + (size_t)row*HID + kq);
                cp16((half*)(smem + HS_OFF + HS_PART_B) + row*HSS + kq, srcL + (size_t)row*HID + kq);
            }
            CP_COMMIT();

            for (int c = 0; c < 8; c++) {
                if (c + 1 < 8) {
                    int bf = (c + 1) & 1;
#pragma unroll
                    for (int i = 0; i < 4; i++) {
                        int qq = tid + NTHR * i, row = qq >> 4, kq = (qq & 15) * 8;
                        cp16((half*)(smem + HS_OFF + (bf*2+0)*HS_PART_B) + row*HSS + kq,
                             srcH + (size_t)row*HID + (c+1)*128 + kq);
                        cp16((half*)(smem + HS_OFF + (bf*2+1)*HS_PART_B) + row*HSS + kq,
                             srcL + (size_t)row*HID + (c+1)*128 + kq);
                    }
                    CP_COMMIT(); CP_WAIT1();
                } else CP_WAIT0();
                __syncthreads();

                const half* hh = (half*)(smem + HS_OFF + ((c&1)*2+0)*HS_PART_B);
                const half* hl = (half*)(smem + HS_OFF + ((c&1)*2+1)*HS_PART_B);
#pragma unroll
                for (int s = 0; s < 8; s++) {
                    const int kb = s * 16, kg = c * 128 + kb;
                    uint32_t Ah[2][4], Al[2][4], Bh[2], Bl[2];
#pragma unroll
                    for (int mt = 0; mt < 2; mt++) {
                        ldsm4(Ah[mt], hh + (mi*32 + mt*16 + (lane&15))*HSS + kb + ((lane>>4)<<3));
                        ldsm4(Al[mt], hl + (mi*32 + mt*16 + (lane&15))*HSS + kb + ((lane>>4)<<3));
                    }
                    ldsm2(Bh, wsh + (ni*8 + (lane&7))*WSS + kg + (((lane>>3)&1)<<3));
                    ldsm2(Bl, wsl + (ni*8 + (lane&7))*WSS + kg + (((lane>>3)&1)<<3));
#pragma unroll
                    for (int mt = 0; mt < 2; mt++) {
                        mma16816(acc[mt], Ah[mt], Bh);
                        mma16816(acc[mt], Ah[mt], Bl);
                        mma16816(acc[mt], Al[mt], Bh);
                    }
                }
                __syncthreads();
            }

            // psum[b][n]
#pragma unroll
            for (int mt = 0; mt < 2; mt++) {
                int row = mi*32 + mt*16 + r, col = ni*8 + q*2;
                *(float2*)(psum + row*34 + col) = make_float2(acc[mt][0], acc[mt][1]);
                *(float2*)(psum + (row+8)*34 + col) = make_float2(acc[mt][2], acc[mt][3]);
            }
            __syncthreads();
        }

        // pointwise cell update: pairs p = tid + 256*qq
        const float* xg_t = xg + (size_t)t * BATCH * G4;
        float* h_out = hseq ? hseq + (size_t)t * BATCH * HID : (float*)0;
        half* hhio = hhi + (size_t)t * BATCH * HID;
        half* hloo = hlo + (size_t)t * BATCH * HID;
#pragma unroll
        for (int qq = 0; qq < 2; qq++) {
            int p = tid + NTHR * qq;
            int b = p >> 3, jl = p & 7, j = j0 + jl;
            const float* xr = xg_t + (size_t)b * G4 + j;
            float ig = xr[0], fg = xr[HID], gg = xr[2*HID], og = xr[3*HID];
            if (t > 0) {
                ig += psum[b*34 + jl];
                fg += psum[b*34 + 8 + jl];
                gg += psum[b*34 + 16 + jl];
                og += psum[b*34 + 24 + jl];
            }
            ig = 1.f / (1.f + expf(-ig));
            fg = 1.f / (1.f + expf(-fg));
            gg = tanhf(gg);
            og = 1.f / (1.f + expf(-og));
            float cn = fg * creg[qq] + ig * gg;
            creg[qq] = cn;
            float hv = og * tanhf(cn);
            size_t idx = (size_t)b * HID + j;
            if (h_out) h_out[idx] = hv;
            half hh = __float2half(hv);
            hhio[idx] = hh;
            hloo[idx] = __float2half(hv - __half2float(hh));
        }
        grid_barrier(nb);
    }
}

// ---------------------------------------------------------------------------
__global__ void final_linear_kernel(const float* __restrict__ h_last,
                                    const float* __restrict__ Wl,
                                    const float* __restrict__ bl,
                                    float* __restrict__ y) {
    int b = blockIdx.x;
    __shared__ float red[128];
    float s = 0.f;
    for (int k = threadIdx.x; k < HID; k += 128)
        s += h_last[(size_t)b * HID + k] * Wl[k];
    red[threadIdx.x] = s;
    __syncthreads();
    for (int off = 64; off > 0; off >>= 1) {
        if (threadIdx.x < off) red[threadIdx.x] += red[threadIdx.x + off];
        __syncthreads();
    }
    if (threadIdx.x == 0) y[b] = red[0] + bl[0];
}

// ---------------------------------------------------------------------------
extern "C" void kernel_launch(void* const* d_in, const int* in_sizes, int n_in,
                              void* d_out, int out_size) {
    (void)in_sizes; (void)n_in; (void)out_size;
    const float* x    = (const float*)d_in[0];
    const float* Wih0 = (const float*)d_in[1];
    const float* Whh0 = (const float*)d_in[2];
    const float* bih0 = (const float*)d_in[3];
    const float* bhh0 = (const float*)d_in[4];
    const float* Wih1 = (const float*)d_in[5];
    const float* Whh1 = (const float*)d_in[6];
    const float* bih1 = (const float*)d_in[7];
    const float* bhh1 = (const float*)d_in[8];
    const float* Wlin = (const float*)d_in[9];
    const float* blin = (const float*)d_in[10];

    float* out      = (float*)d_out;
    float* lstm_out = out;
    float* ypred    = out + (size_t)SEQ * BATCH * HID;

    float *xg; half *hhi, *hlo, *whi, *wlo, *xhi, *xlo;
    cudaGetSymbolAddress((void**)&xg,  g_xg);
    cudaGetSymbolAddress((void**)&hhi, g_h_hi);
    cudaGetSymbolAddress((void**)&hlo, g_h_lo);
    cudaGetSymbolAddress((void**)&whi, g_w_hi);
    cudaGetSymbolAddress((void**)&wlo, g_w_lo);
    cudaGetSymbolAddress((void**)&xhi, g_x_hi);
    cudaGetSymbolAddress((void**)&xlo, g_x_lo);

    cudaFuncSetAttribute(lstm_layer_mma,
                         cudaFuncAttributeMaxDynamicSharedMemorySize, SMEM_TOT);

    const int M = SEQ * BATCH;
    dim3 gg(G4 / 64, M / 64);

    init_bar_kernel<<<1, 1>>>();

    // Layer 0
    int nx = SEQ * BATCH * INP;
    split_fp16_kernel<<<nx/4/256, 256>>>(x, xhi, xlo, nx);
    int nw0 = G4 * INP;
    split_fp16_kernel<<<nw0/4/256, 256>>>(Wih0, whi, wlo, nw0);
    hgemm_split_kernel<<<gg, 256>>>(xhi, xlo, whi, wlo, bih0, bhh0, xg, M, INP);
    lstm_layer_mma<<<NBLK, NTHR, SMEM_TOT>>>(xg, Whh0, hhi, hlo, (float*)0);

    // Layer 1
    int nw1 = G4 * HID;
    split_fp16_kernel<<<nw1/4/256, 256>>>(Wih1, whi, wlo, nw1);
    hgemm_split_kernel<<<gg, 256>>>(hhi, hlo, whi, wlo, bih1, bhh1, xg, M, HID);
    lstm_layer_mma<<<NBLK, NTHR, SMEM_TOT>>>(xg, Whh1, hhi, hlo, lstm_out);

    // Head
    final_linear_kernel<<<BATCH, 128>>>(lstm_out + (size_t)(SEQ-1) * BATCH * HID,
                                        Wlin, blin, ypred);
}

// round 5
// speedup vs baseline: 2.6545x; 1.0567x over previous
#include <cuda_runtime.h>
#include <cuda_fp16.h>
#include <math.h>
#include <stdint.h>

#define SEQ   512
#define BATCH 64
#define INP   64
#define HID   1024
#define G4    (4 * HID)
#define NBLK  128
#define NTHR  256

// ---- static scratch ----
__device__ float g_xg[(size_t)SEQ * BATCH * G4];
__device__ half  g_h_hi[(size_t)SEQ * BATCH * HID];
__device__ half  g_h_lo[(size_t)SEQ * BATCH * HID];
__device__ half  g_w_hi[(size_t)G4 * HID];
__device__ half  g_w_lo[(size_t)G4 * HID];
__device__ half  g_x_hi[(size_t)SEQ * BATCH * INP];
__device__ half  g_x_lo[(size_t)SEQ * BATCH * INP];
__device__ unsigned g_flags[NBLK * 8];   // padded: 32B per CTA
__device__ unsigned g_gen;

// ---- helpers ----
__device__ __forceinline__ void mma16816(float c[4], const uint32_t a[4], const uint32_t b[2]) {
    asm volatile("mma.sync.aligned.m16n8k16.row.col.f32.f16.f16.f32 "
        "{%0,%1,%2,%3}, {%4,%5,%6,%7}, {%8,%9}, {%0,%1,%2,%3};\n"
        : "+f"(c[0]), "+f"(c[1]), "+f"(c[2]), "+f"(c[3])
        : "r"(a[0]), "r"(a[1]), "r"(a[2]), "r"(a[3]), "r"(b[0]), "r"(b[1]));
}
__device__ __forceinline__ void ldsm4(uint32_t r[4], const half* p) {
    uint32_t a = (uint32_t)__cvta_generic_to_shared(p);
    asm volatile("ldmatrix.sync.aligned.m8n8.x4.shared.b16 {%0,%1,%2,%3}, [%4];\n"
        : "=r"(r[0]), "=r"(r[1]), "=r"(r[2]), "=r"(r[3]) : "r"(a));
}
__device__ __forceinline__ void ldsm2(uint32_t r[2], const half* p) {
    uint32_t a = (uint32_t)__cvta_generic_to_shared(p);
    asm volatile("ldmatrix.sync.aligned.m8n8.x2.shared.b16 {%0,%1}, [%2];\n"
        : "=r"(r[0]), "=r"(r[1]) : "r"(a));
}
__device__ __forceinline__ void cp16(void* dst, const void* src) {
    uint32_t d = (uint32_t)__cvta_generic_to_shared(dst);
    asm volatile("cp.async.cg.shared.global [%0], [%1], 16;\n" :: "r"(d), "l"(src));
}
#define CP_COMMIT() asm volatile("cp.async.commit_group;\n")
#define CP_WAIT0()  asm volatile("cp.async.wait_group 0;\n")

__device__ __forceinline__ unsigned ld_acq(const unsigned* p) {
    unsigned v;
    asm volatile("ld.acquire.gpu.u32 %0, [%1];" : "=r"(v) : "l"(p) : "memory");
    return v;
}
__device__ __forceinline__ void st_rel(unsigned* p, unsigned v) {
    asm volatile("st.release.gpu.u32 [%0], %1;" :: "l"(p), "r"(v) : "memory");
}
__device__ __forceinline__ float tanh_fast(float x) {
    float y;
    asm("tanh.approx.f32 %0, %1;" : "=f"(y) : "f"(x));
    return y;
}
__device__ __forceinline__ float sigmoid_fast(float x) {
    return 0.5f * tanh_fast(0.5f * x) + 0.5f;
}

// Load-polling grid barrier. target must be monotonically increasing (step+1).
__device__ __forceinline__ void grid_barrier(unsigned target) {
    if (blockIdx.x == 0) {
        int tid = threadIdx.x;
        if (tid > 0 && tid < NBLK) {
            while (ld_acq(&g_flags[tid * 8]) < target) { }
        }
        __syncthreads();
        if (tid == 0) st_rel(&g_gen, target);
    } else {
        if (threadIdx.x == 0) {
            __threadfence();
            st_rel(&g_flags[blockIdx.x * 8], target);
            while (ld_acq(&g_gen) < target) { }
        }
        __syncthreads();
    }
}

__global__ void init_bar_kernel() {
    int i = threadIdx.x;
    for (int k = i; k < NBLK * 8; k += 256) g_flags[k] = 0u;
    if (i == 0) g_gen = 0u;
}

__global__ void split_fp16_kernel(const float* __restrict__ src,
                                  half* __restrict__ hi, half* __restrict__ lo, int n) {
    int i4 = (blockIdx.x * 256 + threadIdx.x) * 4;
    if (i4 >= n) return;
    float4 v = *(const float4*)(src + i4);
    half h0 = __float2half(v.x), h1 = __float2half(v.y);
    half h2 = __float2half(v.z), h3 = __float2half(v.w);
    hi[i4+0]=h0; hi[i4+1]=h1; hi[i4+2]=h2; hi[i4+3]=h3;
    lo[i4+0]=__float2half(v.x-__half2float(h0));
    lo[i4+1]=__float2half(v.y-__half2float(h1));
    lo[i4+2]=__float2half(v.z-__half2float(h2));
    lo[i4+3]=__float2half(v.w-__half2float(h3));
}

// ---------------------------------------------------------------------------
// C[M][4096] = A[M][K] @ W[4096][K]^T + b1 + b2   (fp16-split, 3-pass mma)
// ---------------------------------------------------------------------------
__global__ void __launch_bounds__(256)
hgemm_split_kernel(const half* __restrict__ Ahi, const half* __restrict__ Alo,
                   const half* __restrict__ Whi, const half* __restrict__ Wlo,
                   const float* __restrict__ b1, const float* __restrict__ b2,
                   float* __restrict__ C, int M, int K) {
    __shared__ half sA[2][2][64 * 40];
    __shared__ half sB[2][2][64 * 40];
    const int tid = threadIdx.x, lane = tid & 31, w = tid >> 5;
    const int mi = w & 1, ni = w >> 1;
    const int r = lane >> 2, q = lane & 3;
    const int m0 = blockIdx.y * 64, n0 = blockIdx.x * 64;
    const int srow = tid >> 2, skq = (tid & 3) * 8;

    float acc[2][2][4];
#pragma unroll
    for (int a = 0; a < 2; a++)
#pragma unroll
        for (int b = 0; b < 2; b++)
#pragma unroll
            for (int c = 0; c < 4; c++) acc[a][b][c] = 0.f;

    const int NIT = K / 32;
    cp16(&sA[0][0][srow*40+skq], Ahi + (size_t)(m0+srow)*K + skq);
    cp16(&sA[0][1][srow*40+skq], Alo + (size_t)(m0+srow)*K + skq);
    cp16(&sB[0][0][srow*40+skq], Whi + (size_t)(n0+srow)*K + skq);
    cp16(&sB[0][1][srow*40+skq], Wlo + (size_t)(n0+srow)*K + skq);
    CP_COMMIT();

    for (int it = 0; it < NIT; it++) {
        CP_WAIT0();
        __syncthreads();
        if (it + 1 < NIT) {
            int k0 = (it+1)*32, bf = (it+1) & 1;
            cp16(&sA[bf][0][srow*40+skq], Ahi + (size_t)(m0+srow)*K + k0 + skq);
            cp16(&sA[bf][1][srow*40+skq], Alo + (size_t)(m0+srow)*K + k0 + skq);
            cp16(&sB[bf][0][srow*40+skq], Whi + (size_t)(n0+srow)*K + k0 + skq);
            cp16(&sB[bf][1][srow*40+skq], Wlo + (size_t)(n0+srow)*K + k0 + skq);
            CP_COMMIT();
        }
        const half *Abh = sA[it&1][0], *Abl = sA[it&1][1];
        const half *Bbh = sB[it&1][0], *Bbl = sB[it&1][1];
#pragma unroll
        for (int s = 0; s < 2; s++) {
            const int kb = s * 16;
            uint32_t Ah[2][4], Al[2][4], Bh[2][2], Bl[2][2];
#pragma unroll
            for (int mt = 0; mt < 2; mt++) {
                ldsm4(Ah[mt], Abh + (mi*32 + mt*16 + (lane&15))*40 + kb + ((lane>>4)<<3));
                ldsm4(Al[mt], Abl + (mi*32 + mt*16 + (lane&15))*40 + kb + ((lane>>4)<<3));
            }
#pragma unroll
            for (int nt = 0; nt < 2; nt++) {
                ldsm2(Bh[nt], Bbh + (ni*16 + nt*8 + (lane&7))*40 + kb + (((lane>>3)&1)<<3));
                ldsm2(Bl[nt], Bbl + (ni*16 + nt*8 + (lane&7))*40 + kb + (((lane>>3)&1)<<3));
            }
#pragma unroll
            for (int mt = 0; mt < 2; mt++)
#pragma unroll
                for (int nt = 0; nt < 2; nt++) {
                    mma16816(acc[mt][nt], Ah[mt], Bh[nt]);
                    mma16816(acc[mt][nt], Ah[mt], Bl[nt]);
                    mma16816(acc[mt][nt], Al[mt], Bh[nt]);
                }
        }
        __syncthreads();
    }
#pragma unroll
    for (int mt = 0; mt < 2; mt++)
#pragma unroll
        for (int nt = 0; nt < 2; nt++) {
            int row = m0 + mi*32 + mt*16 + r;
            int col = n0 + ni*16 + nt*8 + q*2;
            float bs0 = b1[col] + b2[col], bs1 = b1[col+1] + b2[col+1];
            *(float2*)(C + (size_t)row*G4 + col) =
                make_float2(acc[mt][nt][0]+bs0, acc[mt][nt][1]+bs1);
            *(float2*)(C + (size_t)(row+8)*G4 + col) =
                make_float2(acc[mt][nt][2]+bs0, acc[mt][nt][3]+bs1);
        }
}

// ---------------------------------------------------------------------------
// Persistent mma LSTM layer.
// smem: W hi/lo (132096) | h 2buf x hi/lo (69632) | psum (8704) | xgs (8192)
// ---------------------------------------------------------------------------
#define WSS 1032
#define HSS 136
#define WS_PART_B (32 * WSS * 2)
#define HS_PART_B (64 * HSS * 2)
#define HS_OFF    (2 * WS_PART_B)
#define PS_OFF    (HS_OFF + 4 * HS_PART_B)
#define XG_OFF    (PS_OFF + 64 * 34 * 4)
#define SMEM_TOT  (XG_OFF + 64 * 32 * 4)

__global__ void __launch_bounds__(NTHR, 1)
lstm_layer_mma(const float* __restrict__ xg,     // [SEQ][B][4H] incl. biases
               const float* __restrict__ Whh,    // [4H][H] fp32
               half* __restrict__ hhi, half* __restrict__ hlo,  // [SEQ][B][H]
               float* __restrict__ hseq)         // fp32 out or null
{
    extern __shared__ char smem[];
    half*  wsh  = (half*)smem;
    half*  wsl  = (half*)(smem + WS_PART_B);
    float* psum = (float*)(smem + PS_OFF);
    float* xgs  = (float*)(smem + XG_OFF);

    const int tid = threadIdx.x, lane = tid & 31, w = tid >> 5;
    const int mi = w & 1, ni = w >> 1;
    const int r = lane >> 2, q = lane & 3;
    const int j0 = blockIdx.x * 8;

    // one-time: load + split Whh slice into smem (rows n = g*8+jl)
    for (int idx = tid; idx < 32 * 256; idx += NTHR) {
        int n = idx >> 8, kq = (idx & 255) * 4;
        int grow = (n >> 3) * HID + j0 + (n & 7);
        float4 v = *(const float4*)(Whh + (size_t)grow * HID + kq);
        half h0=__float2half(v.x), h1=__float2half(v.y), h2=__float2half(v.z), h3=__float2half(v.w);
        half* ph = wsh + n * WSS + kq;
        half* pl = wsl + n * WSS + kq;
        ph[0]=h0; ph[1]=h1; ph[2]=h2; ph[3]=h3;
        pl[0]=__float2half(v.x-__half2float(h0));
        pl[1]=__float2half(v.y-__half2float(h1));
        pl[2]=__float2half(v.z-__half2float(h2));
        pl[3]=__float2half(v.w-__half2float(h3));
    }

    // stage xg tile for t=0: 512 segments of 16B
#pragma unroll
    for (int i = 0; i < 2; i++) {
        int s = tid * 2 + i;
        int b = s >> 3, g = (s >> 1) & 3, hf = s & 1;
        cp16(xgs + b * 32 + g * 8 + hf * 4,
             xg + (size_t)b * G4 + g * HID + j0 + hf * 4);
    }
    CP_COMMIT();
    __syncthreads();

    float creg[2] = {0.f, 0.f};

    for (int t = 0; t < SEQ; t++) {
        float acc[2][4];
#pragma unroll
        for (int a = 0; a < 2; a++)
#pragma unroll
            for (int c = 0; c < 4; c++) acc[a][c] = 0.f;

        if (t > 0) {
            const half* srcH = hhi + (size_t)(t-1) * BATCH * HID;
            const half* srcL = hlo + (size_t)(t-1) * BATCH * HID;
            // stage chunk 0
#pragma unroll
            for (int i = 0; i < 4; i++) {
                int qq = tid + NTHR * i, row = qq >> 4, kq = (qq & 15) * 8;
                cp16((half*)(smem + HS_OFF) + row*HSS + kq, srcH + (size_t)row*HID + kq);
                cp16((half*)(smem + HS_OFF + HS_PART_B) + row*HSS + kq, srcL + (size_t)row*HID + kq);
            }
            CP_COMMIT();

            for (int c = 0; c < 8; c++) {
                CP_WAIT0();
                __syncthreads();            // chunk c data visible; compute c-1 done
                if (c + 1 < 8) {
                    int bf = (c + 1) & 1;
#pragma unroll
                    for (int i = 0; i < 4; i++) {
                        int qq = tid + NTHR * i, row = qq >> 4, kq = (qq & 15) * 8;
                        cp16((half*)(smem + HS_OFF + (bf*2+0)*HS_PART_B) + row*HSS + kq,
                             srcH + (size_t)row*HID + (c+1)*128 + kq);
                        cp16((half*)(smem + HS_OFF + (bf*2+1)*HS_PART_B) + row*HSS + kq,
                             srcL + (size_t)row*HID + (c+1)*128 + kq);
                    }
                    CP_COMMIT();
                }
                const half* hh = (half*)(smem + HS_OFF + ((c&1)*2+0)*HS_PART_B);
                const half* hl = (half*)(smem + HS_OFF + ((c&1)*2+1)*HS_PART_B);
#pragma unroll
                for (int s = 0; s < 8; s++) {
                    const int kb = s * 16, kg = c * 128 + kb;
                    uint32_t Ah[2][4], Al[2][4], Bh[2], Bl[2];
#pragma unroll
                    for (int mt = 0; mt < 2; mt++) {
                        ldsm4(Ah[mt], hh + (mi*32 + mt*16 + (lane&15))*HSS + kb + ((lane>>4)<<3));
                        ldsm4(Al[mt], hl + (mi*32 + mt*16 + (lane&15))*HSS + kb + ((lane>>4)<<3));
                    }
                    ldsm2(Bh, wsh + (ni*8 + (lane&7))*WSS + kg + (((lane>>3)&1)<<3));
                    ldsm2(Bl, wsl + (ni*8 + (lane&7))*WSS + kg + (((lane>>3)&1)<<3));
#pragma unroll
                    for (int mt = 0; mt < 2; mt++) {
                        mma16816(acc[mt], Ah[mt], Bh);
                        mma16816(acc[mt], Ah[mt], Bl);
                        mma16816(acc[mt], Al[mt], Bh);
                    }
                }
            }
            __syncthreads();   // last chunk compute done before psum overwrite

            // psum[b][n]
#pragma unroll
            for (int mt = 0; mt < 2; mt++) {
                int row = mi*32 + mt*16 + r, col = ni*8 + q*2;
                *(float2*)(psum + row*34 + col) = make_float2(acc[mt][0], acc[mt][1]);
                *(float2*)(psum + (row+8)*34 + col) = make_float2(acc[mt][2], acc[mt][3]);
            }
            __syncthreads();
        } else {
            CP_WAIT0();        // xg tile for t=0
            __syncthreads();
        }

        // pointwise cell update (reads xgs smem + psum smem)
        float* h_out = hseq ? hseq + (size_t)t * BATCH * HID : (float*)0;
        half* hhio = hhi + (size_t)t * BATCH * HID;
        half* hloo = hlo + (size_t)t * BATCH * HID;
#pragma unroll
        for (int qq = 0; qq < 2; qq++) {
            int p = tid + NTHR * qq;
            int b = p >> 3, jl = p & 7, j = j0 + jl;
            const float* xr = xgs + b * 32 + jl;
            float ig = xr[0], fg = xr[8], gg = xr[16], og = xr[24];
            if (t > 0) {
                ig += psum[b*34 + jl];
                fg += psum[b*34 + 8 + jl];
                gg += psum[b*34 + 16 + jl];
                og += psum[b*34 + 24 + jl];
            }
            ig = sigmoid_fast(ig);
            fg = sigmoid_fast(fg);
            gg = tanh_fast(gg);
            og = sigmoid_fast(og);
            float cn = fg * creg[qq] + ig * gg;
            creg[qq] = cn;
            float hv = og * tanh_fast(cn);
            size_t idx = (size_t)b * HID + j;
            if (h_out) h_out[idx] = hv;
            half hh = __float2half(hv);
            hhio[idx] = hh;
            hloo[idx] = __float2half(hv - __half2float(hh));
        }
        __syncthreads();       // xgs readers done before prefetching t+1

        if (t + 1 < SEQ) {
            const float* xgn = xg + (size_t)(t + 1) * BATCH * G4;
#pragma unroll
            for (int i = 0; i < 2; i++) {
                int s = tid * 2 + i;
                int b = s >> 3, g = (s >> 1) & 3, hf = s & 1;
                cp16(xgs + b * 32 + g * 8 + hf * 4,
                     xgn + (size_t)b * G4 + g * HID + j0 + hf * 4);
            }
            CP_COMMIT();
        }
        grid_barrier((unsigned)(t + 1));
    }
}

// ---------------------------------------------------------------------------
__global__ void final_linear_kernel(const float* __restrict__ h_last,
                                    const float* __restrict__ Wl,
                                    const float* __restrict__ bl,
                                    float* __restrict__ y) {
    int b = blockIdx.x;
    __shared__ float red[128];
    float s = 0.f;
    for (int k = threadIdx.x; k < HID; k += 128)
        s += h_last[(size_t)b * HID + k] * Wl[k];
    red[threadIdx.x] = s;
    __syncthreads();
    for (int off = 64; off > 0; off >>= 1) {
        if (threadIdx.x < off) red[threadIdx.x] += red[threadIdx.x + off];
        __syncthreads();
    }
    if (threadIdx.x == 0) y[b] = red[0] + bl[0];
}

// ---------------------------------------------------------------------------
extern "C" void kernel_launch(void* const* d_in, const int* in_sizes, int n_in,
                              void* d_out, int out_size) {
    (void)in_sizes; (void)n_in; (void)out_size;
    const float* x    = (const float*)d_in[0];
    const float* Wih0 = (const float*)d_in[1];
    const float* Whh0 = (const float*)d_in[2];
    const float* bih0 = (const float*)d_in[3];
    const float* bhh0 = (const float*)d_in[4];
    const float* Wih1 = (const float*)d_in[5];
    const float* Whh1 = (const float*)d_in[6];
    const float* bih1 = (const float*)d_in[7];
    const float* bhh1 = (const float*)d_in[8];
    const float* Wlin = (const float*)d_in[9];
    const float* blin = (const float*)d_in[10];

    float* out      = (float*)d_out;
    float* lstm_out = out;
    float* ypred    = out + (size_t)SEQ * BATCH * HID;

    float *xg; half *hhi, *hlo, *whi, *wlo, *xhi, *xlo;
    cudaGetSymbolAddress((void**)&xg,  g_xg);
    cudaGetSymbolAddress((void**)&hhi, g_h_hi);
    cudaGetSymbolAddress((void**)&hlo, g_h_lo);
    cudaGetSymbolAddress((void**)&whi, g_w_hi);
    cudaGetSymbolAddress((void**)&wlo, g_w_lo);
    cudaGetSymbolAddress((void**)&xhi, g_x_hi);
    cudaGetSymbolAddress((void**)&xlo, g_x_lo);

    cudaFuncSetAttribute(lstm_layer_mma,
                         cudaFuncAttributeMaxDynamicSharedMemorySize, SMEM_TOT);

    const int M = SEQ * BATCH;
    dim3 gg(G4 / 64, M / 64);

    // Layer 0
    int nx = SEQ * BATCH * INP;
    split_fp16_kernel<<<nx/4/256, 256>>>(x, xhi, xlo, nx);
    int nw0 = G4 * INP;
    split_fp16_kernel<<<nw0/4/256, 256>>>(Wih0, whi, wlo, nw0);
    hgemm_split_kernel<<<gg, 256>>>(xhi, xlo, whi, wlo, bih0, bhh0, xg, M, INP);
    init_bar_kernel<<<1, 256>>>();
    lstm_layer_mma<<<NBLK, NTHR, SMEM_TOT>>>(xg, Whh0, hhi, hlo, (float*)0);

    // Layer 1
    int nw1 = G4 * HID;
    split_fp16_kernel<<<nw1/4/256, 256>>>(Wih1, whi, wlo, nw1);
    hgemm_split_kernel<<<gg, 256>>>(hhi, hlo, whi, wlo, bih1, bhh1, xg, M, HID);
    init_bar_kernel<<<1, 256>>>();
    lstm_layer_mma<<<NBLK, NTHR, SMEM_TOT>>>(xg, Whh1, hhi, hlo, lstm_out);

    // Head
    final_linear_kernel<<<BATCH, 128>>>(lstm_out + (size_t)(SEQ-1) * BATCH * HID,
                                        Wlin, blin, ypred);
}